// round 1
// baseline (speedup 1.0000x reference)
#include <cuda_runtime.h>

// Closed form of the 4-qubit circuit:
//   theta_i = x[b,i] + w[i],  c_i = cos(2*theta_i)
//   out[b] = { c1*c2*c3, c0*c1, c0*c1*c2, c0*c1*c2*c3 }
// Derivation: product state through RYs (2D rotations compose by angle
// addition), CNOT chain is GF(2)-linear => probs@Z factorizes into
// per-qubit cos(2*theta) products over compile-time bitsets.

__global__ void __launch_bounds__(256)
hilbert_closed_form(const float4* __restrict__ x4,
                    const float* __restrict__ w,
                    float4* __restrict__ out4,
                    int n)
{
    int i = blockIdx.x * blockDim.x + threadIdx.x;
    if (i >= n) return;

    // weights broadcast: L1-resident after first access
    float w0 = w[0], w1 = w[1], w2 = w[2], w3 = w[3];

    float4 xv = x4[i];

    float c0 = cosf(2.0f * (xv.x + w0));
    float c1 = cosf(2.0f * (xv.y + w1));
    float c2 = cosf(2.0f * (xv.z + w2));
    float c3 = cosf(2.0f * (xv.w + w3));

    float t01  = c0 * c1;
    float t012 = t01 * c2;

    float4 o;
    o.x = c1 * c2 * c3;
    o.y = t01;
    o.z = t012;
    o.w = t012 * c3;

    out4[i] = o;
}

extern "C" void kernel_launch(void* const* d_in, const int* in_sizes, int n_in,
                              void* d_out, int out_size)
{
    // metadata order: x (BATCH*4 floats), weights (4 floats).
    // Be defensive: pick the big buffer as x.
    const float* x = (const float*)d_in[0];
    const float* w = (const float*)d_in[1];
    int nx = in_sizes[0];
    if (n_in >= 2 && in_sizes[0] < in_sizes[1]) {
        x = (const float*)d_in[1];
        w = (const float*)d_in[0];
        nx = in_sizes[1];
    }

    int n = nx / 4;  // batch elements
    int threads = 256;
    int blocks = (n + threads - 1) / threads;

    hilbert_closed_form<<<blocks, threads>>>(
        (const float4*)x, w, (float4*)d_out, n);
}